// round 1
// baseline (speedup 1.0000x reference)
#include <cuda_runtime.h>
#include <cuda_bf16.h>
#include <cstdint>
#include <cstddef>

#define NDIM 4096
#define BT   128     // C block tile (128x128)
#define KT   32      // k tile per mainloop iteration
#define SST  40      // smem row stride in bf16 elements (80B: 16B-aligned, conflict-free)

// Scratch: bf16 hi/lo splits. B is stored TRANSPOSED ([n][k]) so both operands
// are k-contiguous in smem and fragment loads are identical for A and B.
static __device__ __nv_bfloat16 g_Ah[(size_t)NDIM * NDIM];
static __device__ __nv_bfloat16 g_Al[(size_t)NDIM * NDIM];
static __device__ __nv_bfloat16 g_Bh[(size_t)NDIM * NDIM];  // [n][k]
static __device__ __nv_bfloat16 g_Bl[(size_t)NDIM * NDIM];  // [n][k]

// ---------------------------------------------------------------------------
// Pre-pass 1: elementwise split of A into bf16 hi + bf16 lo (residual).
// ---------------------------------------------------------------------------
__global__ void convA_kernel(const float* __restrict__ A) {
    size_t i = (size_t)blockIdx.x * blockDim.x + threadIdx.x;  // index of float4
    const float4 v = reinterpret_cast<const float4*>(A)[i];

    __nv_bfloat16 h0 = __float2bfloat16(v.x);
    __nv_bfloat16 h1 = __float2bfloat16(v.y);
    __nv_bfloat16 h2 = __float2bfloat16(v.z);
    __nv_bfloat16 h3 = __float2bfloat16(v.w);
    __nv_bfloat16 l0 = __float2bfloat16(v.x - __bfloat162float(h0));
    __nv_bfloat16 l1 = __float2bfloat16(v.y - __bfloat162float(h1));
    __nv_bfloat16 l2 = __float2bfloat16(v.z - __bfloat162float(h2));
    __nv_bfloat16 l3 = __float2bfloat16(v.w - __bfloat162float(h3));

    ushort4 H = make_ushort4(__bfloat16_as_ushort(h0), __bfloat16_as_ushort(h1),
                             __bfloat16_as_ushort(h2), __bfloat16_as_ushort(h3));
    ushort4 L = make_ushort4(__bfloat16_as_ushort(l0), __bfloat16_as_ushort(l1),
                             __bfloat16_as_ushort(l2), __bfloat16_as_ushort(l3));
    reinterpret_cast<ushort4*>(g_Ah)[i] = H;
    reinterpret_cast<ushort4*>(g_Al)[i] = L;
}

// ---------------------------------------------------------------------------
// Pre-pass 2: split + transpose B. B is [k][n] row-major; emit Bt[n][k].
// Standard 32x32 smem tile transpose (33-wide to kill bank conflicts).
// ---------------------------------------------------------------------------
__global__ void convB_kernel(const float* __restrict__ B) {
    __shared__ float tile[32][33];
    const int bk = blockIdx.x * 32;   // k block
    const int bn = blockIdx.y * 32;   // n block
    const int x = threadIdx.x;        // 0..31

    #pragma unroll
    for (int yy = threadIdx.y; yy < 32; yy += 8)
        tile[yy][x] = B[(size_t)(bk + yy) * NDIM + bn + x];
    __syncthreads();

    #pragma unroll
    for (int yy = threadIdx.y; yy < 32; yy += 8) {
        const int n = bn + yy;
        const int k = bk + x;
        const float v = tile[x][yy];            // = B[k][n]
        const __nv_bfloat16 h = __float2bfloat16(v);
        const __nv_bfloat16 l = __float2bfloat16(v - __bfloat162float(h));
        g_Bh[(size_t)n * NDIM + k] = h;
        g_Bl[(size_t)n * NDIM + k] = l;
    }
}

// ---------------------------------------------------------------------------
// Triangular block GEMM: C[bm,bn] for bm >= bn, k in [bn*128, (bm+1)*128).
// 256 threads, warp tile 64x32, mma.sync.m16n8k16 bf16, fp32 accum.
// Per k16 step: acc += Ah*Bh + Ah*Bl + Al*Bh  (shared accumulator).
// ---------------------------------------------------------------------------
__device__ __forceinline__ void cpa16(uint32_t dst_sh, const void* src) {
    asm volatile("cp.async.cg.shared.global [%0], [%1], 16;\n" ::"r"(dst_sh), "l"(src));
}

#define MMA_BF16(d, a, b)                                                              \
    asm volatile(                                                                      \
        "mma.sync.aligned.m16n8k16.row.col.f32.bf16.bf16.f32 "                         \
        "{%0,%1,%2,%3}, {%4,%5,%6,%7}, {%8,%9}, {%0,%1,%2,%3};\n"                      \
        : "+f"((d)[0]), "+f"((d)[1]), "+f"((d)[2]), "+f"((d)[3])                       \
        : "r"((a)[0]), "r"((a)[1]), "r"((a)[2]), "r"((a)[3]), "r"((b)[0]), "r"((b)[1]))

__global__ __launch_bounds__(256, 2) void trimm_kernel(float* __restrict__ C) {
    __shared__ __nv_bfloat16 sAh[BT * SST];
    __shared__ __nv_bfloat16 sAl[BT * SST];
    __shared__ __nv_bfloat16 sBh[BT * SST];
    __shared__ __nv_bfloat16 sBl[BT * SST];

    // Decode linear block id -> (bm, bn) in the lower triangle.
    const int t = blockIdx.x;
    int bm = (int)((sqrtf(8.0f * (float)t + 1.0f) - 1.0f) * 0.5f);
    while ((bm + 1) * (bm + 2) / 2 <= t) ++bm;
    while (bm * (bm + 1) / 2 > t) --bm;
    const int bn = t - bm * (bm + 1) / 2;

    const int m0 = bm * BT, n0 = bn * BT;
    const int kbeg = n0;            // B tril: k >= n
    const int kend = m0 + BT;       // A tril: k <= m

    const int tid  = threadIdx.x;
    const int warp = tid >> 5, lane = tid & 31;
    const int wm = (warp >> 2) * 64;   // 2 warps along m
    const int wn = (warp & 3) * 32;    // 4 warps along n
    const int g  = lane >> 2, tg = lane & 3;

    float acc[4][4][4];
    #pragma unroll
    for (int mi = 0; mi < 4; mi++)
        #pragma unroll
        for (int ni = 0; ni < 4; ni++)
            #pragma unroll
            for (int r = 0; r < 4; r++) acc[mi][ni][r] = 0.0f;

    // cp.async mapping: 2 threads per row; each thread moves 32B (2x16B) per tile.
    const int lr = tid >> 1;        // row 0..127
    const int lh = tid & 1;         // which 32B half of the 64B row
    const __nv_bfloat16* gAh = g_Ah + (size_t)(m0 + lr) * NDIM;
    const __nv_bfloat16* gAl = g_Al + (size_t)(m0 + lr) * NDIM;
    const __nv_bfloat16* gBh = g_Bh + (size_t)(n0 + lr) * NDIM;
    const __nv_bfloat16* gBl = g_Bl + (size_t)(n0 + lr) * NDIM;

    const uint32_t doff = (uint32_t)((lr * SST + lh * 16) * 2);  // bytes
    const uint32_t dAh = (uint32_t)__cvta_generic_to_shared(sAh) + doff;
    const uint32_t dAl = (uint32_t)__cvta_generic_to_shared(sAl) + doff;
    const uint32_t dBh = (uint32_t)__cvta_generic_to_shared(sBh) + doff;
    const uint32_t dBl = (uint32_t)__cvta_generic_to_shared(sBl) + doff;

    for (int k0 = kbeg; k0 < kend; k0 += KT) {
        const int co = k0 + lh * 16;
        cpa16(dAh,      gAh + co);
        cpa16(dAh + 16, gAh + co + 8);
        cpa16(dAl,      gAl + co);
        cpa16(dAl + 16, gAl + co + 8);
        cpa16(dBh,      gBh + co);
        cpa16(dBh + 16, gBh + co + 8);
        cpa16(dBl,      gBl + co);
        cpa16(dBl + 16, gBl + co + 8);
        asm volatile("cp.async.commit_group;\n");
        asm volatile("cp.async.wait_group 0;\n");
        __syncthreads();

        #pragma unroll
        for (int s = 0; s < 2; s++) {
            const int kk = s * 16;
            uint32_t a[4][4], bh[4][2], bl[4][2];

            #pragma unroll
            for (int mi = 0; mi < 4; mi++) {
                const int base = (wm + mi * 16 + g) * SST + kk + tg * 2;
                a[mi][0] = *(const uint32_t*)(sAh + base);
                a[mi][1] = *(const uint32_t*)(sAh + base + 8 * SST);
                a[mi][2] = *(const uint32_t*)(sAh + base + 8);
                a[mi][3] = *(const uint32_t*)(sAh + base + 8 * SST + 8);
            }
            #pragma unroll
            for (int ni = 0; ni < 4; ni++) {
                const int base = (wn + ni * 8 + g) * SST + kk + tg * 2;
                bh[ni][0] = *(const uint32_t*)(sBh + base);
                bh[ni][1] = *(const uint32_t*)(sBh + base + 8);
                bl[ni][0] = *(const uint32_t*)(sBl + base);
                bl[ni][1] = *(const uint32_t*)(sBl + base + 8);
            }

            // Ah*Bh + Ah*Bl
            #pragma unroll
            for (int mi = 0; mi < 4; mi++)
                #pragma unroll
                for (int ni = 0; ni < 4; ni++) {
                    MMA_BF16(acc[mi][ni], a[mi], bh[ni]);
                    MMA_BF16(acc[mi][ni], a[mi], bl[ni]);
                }

            // Reload a <- Al (hi fragments dead), then Al*Bh
            #pragma unroll
            for (int mi = 0; mi < 4; mi++) {
                const int base = (wm + mi * 16 + g) * SST + kk + tg * 2;
                a[mi][0] = *(const uint32_t*)(sAl + base);
                a[mi][1] = *(const uint32_t*)(sAl + base + 8 * SST);
                a[mi][2] = *(const uint32_t*)(sAl + base + 8);
                a[mi][3] = *(const uint32_t*)(sAl + base + 8 * SST + 8);
            }
            #pragma unroll
            for (int mi = 0; mi < 4; mi++)
                #pragma unroll
                for (int ni = 0; ni < 4; ni++)
                    MMA_BF16(acc[mi][ni], a[mi], bh[ni]);
        }
        __syncthreads();
    }

    // Epilogue: fp32 stores (upper-triangle blocks already zeroed by memset).
    #pragma unroll
    for (int mi = 0; mi < 4; mi++)
        #pragma unroll
        for (int ni = 0; ni < 4; ni++) {
            const int r0 = m0 + wm + mi * 16 + g;
            const int c0 = n0 + wn + ni * 8 + tg * 2;
            *reinterpret_cast<float2*>(C + (size_t)r0 * NDIM + c0) =
                make_float2(acc[mi][ni][0], acc[mi][ni][1]);
            *reinterpret_cast<float2*>(C + (size_t)(r0 + 8) * NDIM + c0) =
                make_float2(acc[mi][ni][2], acc[mi][ni][3]);
        }
}

// ---------------------------------------------------------------------------
extern "C" void kernel_launch(void* const* d_in, const int* in_sizes, int n_in,
                              void* d_out, int out_size) {
    (void)in_sizes; (void)n_in; (void)out_size;
    const float* A = (const float*)d_in[0];
    const float* B = (const float*)d_in[1];
    float* C = (float*)d_out;

    // Zero output: upper-triangle blocks are never written by the GEMM.
    cudaMemsetAsync(d_out, 0, (size_t)NDIM * NDIM * sizeof(float), 0);

    // Splits
    convA_kernel<<<(NDIM * (size_t)NDIM) / 4 / 256, 256>>>(A);
    convB_kernel<<<dim3(NDIM / 32, NDIM / 32), dim3(32, 8)>>>(B);

    // Triangular GEMM: 32*33/2 = 528 blocks
    trimm_kernel<<<528, 256>>>(C);
}

// round 3
// speedup vs baseline: 1.9374x; 1.9374x over previous
#include <cuda_runtime.h>
#include <cuda_fp16.h>
#include <cstdint>
#include <cstddef>

#define NDIM   4096
#define BT     128           // C tile 128x128
#define KT     32            // k elements per pipeline stage
#define STAGES 5
#define SROW   80            // smem bytes per tile row (64B data + 16B pad: conflict-free)
#define TILE_B (128 * SROW)            // 10240 B
#define STAGE_B (3 * TILE_B)           // Ah, Al, Bh = 30720 B
#define DSMEM_BYTES (STAGES * STAGE_B) // 153600 B

#define AL_SCALE 2048.0f
#define AL_INV   (1.0f / 2048.0f)

// fp16 split scratch. B transposed to [n][k]; only hi half of B is needed
// (the dropped A·(B-Bh) term is the accuracy budget: ~2.8e-4 rel).
static __device__ __half g_Ah[(size_t)NDIM * NDIM];
static __device__ __half g_Al[(size_t)NDIM * NDIM];   // (A - Ah) * 2048
static __device__ __half g_Bh[(size_t)NDIM * NDIM];   // [n][k]

// ---------------------------------------------------------------------------
// Pre-pass 1: A -> fp16 hi + scaled fp16 residual.
// ---------------------------------------------------------------------------
__global__ void convA_kernel(const float* __restrict__ A) {
    size_t i = (size_t)blockIdx.x * blockDim.x + threadIdx.x;  // float4 index
    const float4 v = reinterpret_cast<const float4*>(A)[i];
    __half h0 = __float2half(v.x), h1 = __float2half(v.y);
    __half h2 = __float2half(v.z), h3 = __float2half(v.w);
    __half l0 = __float2half((v.x - __half2float(h0)) * AL_SCALE);
    __half l1 = __float2half((v.y - __half2float(h1)) * AL_SCALE);
    __half l2 = __float2half((v.z - __half2float(h2)) * AL_SCALE);
    __half l3 = __float2half((v.w - __half2float(h3)) * AL_SCALE);
    reinterpret_cast<ushort4*>(g_Ah)[i] =
        make_ushort4(__half_as_ushort(h0), __half_as_ushort(h1),
                     __half_as_ushort(h2), __half_as_ushort(h3));
    reinterpret_cast<ushort4*>(g_Al)[i] =
        make_ushort4(__half_as_ushort(l0), __half_as_ushort(l1),
                     __half_as_ushort(l2), __half_as_ushort(l3));
}

// ---------------------------------------------------------------------------
// Pre-pass 2: transpose B[k][n] -> Bh[n][k] (fp16).
// ---------------------------------------------------------------------------
__global__ void convB_kernel(const float* __restrict__ B) {
    __shared__ float tile[32][33];
    const int bk = blockIdx.x * 32, bn = blockIdx.y * 32;
    const int x = threadIdx.x;
    #pragma unroll
    for (int yy = threadIdx.y; yy < 32; yy += 8)
        tile[yy][x] = B[(size_t)(bk + yy) * NDIM + bn + x];
    __syncthreads();
    #pragma unroll
    for (int yy = threadIdx.y; yy < 32; yy += 8)
        g_Bh[(size_t)(bn + yy) * NDIM + bk + x] = __float2half(tile[x][yy]);
}

// ---------------------------------------------------------------------------
__device__ __forceinline__ uint32_t smem_u32(const void* p) {
    uint32_t a;
    asm("{ .reg .u64 t; cvta.to.shared.u64 t, %1; cvt.u32.u64 %0, t; }" : "=r"(a) : "l"(p));
    return a;
}
__device__ __forceinline__ void cpa16(uint32_t dst, const void* src) {
    asm volatile("cp.async.cg.shared.global [%0], [%1], 16;\n" ::"r"(dst), "l"(src));
}

#define LDSM4(r0, r1, r2, r3, addr)                                                    \
    asm volatile("ldmatrix.sync.aligned.m8n8.x4.shared.b16 {%0,%1,%2,%3}, [%4];"       \
                 : "=r"(r0), "=r"(r1), "=r"(r2), "=r"(r3) : "r"(addr))

#define MMA_F16(d, a, b0, b1)                                                          \
    asm volatile(                                                                      \
        "mma.sync.aligned.m16n8k16.row.col.f32.f16.f16.f32 "                           \
        "{%0,%1,%2,%3}, {%4,%5,%6,%7}, {%8,%9}, {%0,%1,%2,%3};\n"                      \
        : "+f"((d)[0]), "+f"((d)[1]), "+f"((d)[2]), "+f"((d)[3])                       \
        : "r"((a)[0]), "r"((a)[1]), "r"((a)[2]), "r"((a)[3]), "r"(b0), "r"(b1))

// ---------------------------------------------------------------------------
// Triangular GEMM, 2-pass fp16 split, 5-stage cp.async pipeline.
// Grid: 1024 CTAs = 528 lower-triangle tiles (bm-descending LPT order)
//                 + 496 upper tiles that just write zeros.
// ---------------------------------------------------------------------------
__global__ __launch_bounds__(512, 1) void trimm_kernel(float* __restrict__ C) {
    extern __shared__ char dsm[];
    const int tid = threadIdx.x;
    const int lane = tid & 31, warp = tid >> 5;

    if (blockIdx.x >= 528) {
        // Upper-triangle tile: zero fill.
        int u = blockIdx.x - 528, r = 0;
        #pragma unroll 1
        while (u >= 31 - r) { u -= 31 - r; r++; }
        const int m0 = r * BT, n0 = (r + 1 + u) * BT;
        const float4 z = make_float4(0.f, 0.f, 0.f, 0.f);
        #pragma unroll
        for (int i = tid; i < 128 * 32; i += 512)
            reinterpret_cast<float4*>(C + (size_t)(m0 + (i >> 5)) * NDIM + n0)[i & 31] = z;
        return;
    }

    // Lower-triangle tile, bm descending (LPT + strip reuse).
    int t = blockIdx.x, bm = 31;
    #pragma unroll 1
    while (t >= bm + 1) { t -= bm + 1; bm--; }
    const int bn = t;
    const int m0 = bm * BT, n0 = bn * BT;
    const int kbeg = n0;                          // B tril: k >= n
    const int T = (m0 + BT - kbeg) / KT;          // chunks; min 4

    const uint32_t sb = smem_u32(dsm);

    // cp.async mapping: thread -> (row, 16B chunk); 1 cp per tile per thread.
    const int cr = tid >> 2, cc = tid & 3;
    const __half* gAh = g_Ah + (size_t)(m0 + cr) * NDIM + cc * 8;
    const __half* gAl = g_Al + (size_t)(m0 + cr) * NDIM + cc * 8;
    const __half* gBh = g_Bh + (size_t)(n0 + cr) * NDIM + cc * 8;
    const uint32_t cdst = sb + cr * SROW + cc * 16;

    // Warp tile: 32m x 32n; grid 4x4 warps.
    const int wm = (warp >> 2) * 32, wn = (warp & 3) * 32;
    // ldmatrix lane address offsets (bytes, within a tile, before k offset).
    uint32_t a_off[2], b_off[2];
    #pragma unroll
    for (int mi = 0; mi < 2; mi++)
        a_off[mi] = (uint32_t)((wm + mi * 16 + (lane & 15)) * SROW + (lane >> 4) * 16);
    #pragma unroll
    for (int p = 0; p < 2; p++) {
        const int quad = lane >> 3;
        b_off[p] = (uint32_t)((wn + p * 16 + (quad >> 1) * 8 + (lane & 7)) * SROW +
                              (quad & 1) * 16);
    }

    float acc1[2][4][4], acc2[2][4][4];
    #pragma unroll
    for (int mi = 0; mi < 2; mi++)
        #pragma unroll
        for (int ni = 0; ni < 4; ni++)
            #pragma unroll
            for (int r = 0; r < 4; r++) { acc1[mi][ni][r] = 0.f; acc2[mi][ni][r] = 0.f; }

    // Prologue: fill STAGES-1 = 4 slots (T >= 4 always).
    #pragma unroll
    for (int s = 0; s < STAGES - 1; s++) {
        const int k0 = kbeg + s * KT;
        const uint32_t d = cdst + s * STAGE_B;
        cpa16(d, gAh + k0);
        cpa16(d + TILE_B, gAl + k0);
        cpa16(d + 2 * TILE_B, gBh + k0);
        asm volatile("cp.async.commit_group;\n");
    }

    #pragma unroll 1
    for (int it = 0; it < T; it++) {
        __syncthreads();  // everyone done computing chunk it-1 (its slot gets reloaded)
        const int ch = it + STAGES - 1;
        if (ch < T) {
            const int k0 = kbeg + ch * KT;
            const uint32_t d = cdst + (ch % STAGES) * STAGE_B;
            cpa16(d, gAh + k0);
            cpa16(d + TILE_B, gAl + k0);
            cpa16(d + 2 * TILE_B, gBh + k0);
        }
        asm volatile("cp.async.commit_group;\n");
        asm volatile("cp.async.wait_group %0;\n" ::"n"(STAGES - 2));
        __syncthreads();  // chunk `it` visible to all warps

        const uint32_t st = sb + (it % STAGES) * STAGE_B;
        #pragma unroll
        for (int kk = 0; kk < 2; kk++) {
            const uint32_t kb = kk * 32;  // 16 halfwords = 32 bytes
            uint32_t ah[2][4], al[2][4], bb[2][4];
            LDSM4(ah[0][0], ah[0][1], ah[0][2], ah[0][3], st + a_off[0] + kb);
            LDSM4(ah[1][0], ah[1][1], ah[1][2], ah[1][3], st + a_off[1] + kb);
            LDSM4(al[0][0], al[0][1], al[0][2], al[0][3], st + TILE_B + a_off[0] + kb);
            LDSM4(al[1][0], al[1][1], al[1][2], al[1][3], st + TILE_B + a_off[1] + kb);
            LDSM4(bb[0][0], bb[0][1], bb[0][2], bb[0][3], st + 2 * TILE_B + b_off[0] + kb);
            LDSM4(bb[1][0], bb[1][1], bb[1][2], bb[1][3], st + 2 * TILE_B + b_off[1] + kb);
            #pragma unroll
            for (int mi = 0; mi < 2; mi++)
                #pragma unroll
                for (int p = 0; p < 2; p++) {
                    MMA_F16(acc1[mi][2 * p],     ah[mi], bb[p][0], bb[p][1]);
                    MMA_F16(acc1[mi][2 * p + 1], ah[mi], bb[p][2], bb[p][3]);
                    MMA_F16(acc2[mi][2 * p],     al[mi], bb[p][0], bb[p][1]);
                    MMA_F16(acc2[mi][2 * p + 1], al[mi], bb[p][2], bb[p][3]);
                }
        }
    }

    // Epilogue: C = acc1 + acc2/2048.
    const int g = lane >> 2, tg = lane & 3;
    #pragma unroll
    for (int mi = 0; mi < 2; mi++)
        #pragma unroll
        for (int ni = 0; ni < 4; ni++) {
            const int r0 = m0 + wm + mi * 16 + g;
            const int c0 = n0 + wn + ni * 8 + tg * 2;
            float* d0 = C + (size_t)r0 * NDIM + c0;
            float* d1 = C + (size_t)(r0 + 8) * NDIM + c0;
            *reinterpret_cast<float2*>(d0) =
                make_float2(acc1[mi][ni][0] + acc2[mi][ni][0] * AL_INV,
                            acc1[mi][ni][1] + acc2[mi][ni][1] * AL_INV);
            *reinterpret_cast<float2*>(d1) =
                make_float2(acc1[mi][ni][2] + acc2[mi][ni][2] * AL_INV,
                            acc1[mi][ni][3] + acc2[mi][ni][3] * AL_INV);
        }
}

// ---------------------------------------------------------------------------
extern "C" void kernel_launch(void* const* d_in, const int* in_sizes, int n_in,
                              void* d_out, int out_size) {
    (void)in_sizes; (void)n_in; (void)out_size;
    const float* A = (const float*)d_in[0];
    const float* B = (const float*)d_in[1];
    float* C = (float*)d_out;

    static bool attr_done = false;
    if (!attr_done) {
        cudaFuncSetAttribute(trimm_kernel, cudaFuncAttributeMaxDynamicSharedMemorySize,
                             DSMEM_BYTES);
        attr_done = true;
    }

    convA_kernel<<<(NDIM * (size_t)NDIM) / 4 / 256, 256>>>(A);
    convB_kernel<<<dim3(NDIM / 32, NDIM / 32), dim3(32, 8)>>>(B);
    trimm_kernel<<<1024, 512, DSMEM_BYTES>>>(C);
}

// round 4
// speedup vs baseline: 3.1954x; 1.6494x over previous
#include <cuda_runtime.h>
#include <cuda_fp16.h>
#include <cstdint>
#include <cstddef>

#define NDIM   4096
#define BT     128            // C tile 128x128
#define KT     64             // k elements per pipeline stage
#define STAGES 5
#define SROW   144            // smem bytes per tile row (128B data + 16B pad)
#define TILE_B (128 * SROW)   // 18432 B
#define STAGE_B (2 * TILE_B)  // Ah + Bh = 36864 B
#define DSMEM_BYTES (STAGES * STAGE_B)  // 184320 B

// Single-pass fp16 scratch. B transposed to [n][k].
static __device__ __half g_Ah[(size_t)NDIM * NDIM];
static __device__ __half g_Bh[(size_t)NDIM * NDIM];   // [n][k]

// ---------------------------------------------------------------------------
// Pre-pass 1: A -> fp16.
// ---------------------------------------------------------------------------
__global__ void convA_kernel(const float* __restrict__ A) {
    size_t i = (size_t)blockIdx.x * blockDim.x + threadIdx.x;  // float4 index
    const float4 v = reinterpret_cast<const float4*>(A)[i];
    reinterpret_cast<ushort4*>(g_Ah)[i] =
        make_ushort4(__half_as_ushort(__float2half(v.x)),
                     __half_as_ushort(__float2half(v.y)),
                     __half_as_ushort(__float2half(v.z)),
                     __half_as_ushort(__float2half(v.w)));
}

// ---------------------------------------------------------------------------
// Pre-pass 2: transpose B[k][n] -> Bh[n][k] (fp16).
// ---------------------------------------------------------------------------
__global__ void convB_kernel(const float* __restrict__ B) {
    __shared__ float tile[32][33];
    const int bk = blockIdx.x * 32, bn = blockIdx.y * 32;
    const int x = threadIdx.x;
    #pragma unroll
    for (int yy = threadIdx.y; yy < 32; yy += 8)
        tile[yy][x] = B[(size_t)(bk + yy) * NDIM + bn + x];
    __syncthreads();
    #pragma unroll
    for (int yy = threadIdx.y; yy < 32; yy += 8)
        g_Bh[(size_t)(bn + yy) * NDIM + bk + x] = __float2half(tile[x][yy]);
}

// ---------------------------------------------------------------------------
__device__ __forceinline__ uint32_t smem_u32(const void* p) {
    uint32_t a;
    asm("{ .reg .u64 t; cvta.to.shared.u64 t, %1; cvt.u32.u64 %0, t; }" : "=r"(a) : "l"(p));
    return a;
}
__device__ __forceinline__ void cpa16(uint32_t dst, const void* src) {
    asm volatile("cp.async.cg.shared.global [%0], [%1], 16;\n" ::"r"(dst), "l"(src));
}

#define LDSM4(r0, r1, r2, r3, addr)                                                    \
    asm volatile("ldmatrix.sync.aligned.m8n8.x4.shared.b16 {%0,%1,%2,%3}, [%4];"       \
                 : "=r"(r0), "=r"(r1), "=r"(r2), "=r"(r3) : "r"(addr))

#define MMA_F16(d, a, b0, b1)                                                          \
    asm volatile(                                                                      \
        "mma.sync.aligned.m16n8k16.row.col.f32.f16.f16.f32 "                           \
        "{%0,%1,%2,%3}, {%4,%5,%6,%7}, {%8,%9}, {%0,%1,%2,%3};\n"                      \
        : "+f"((d)[0]), "+f"((d)[1]), "+f"((d)[2]), "+f"((d)[3])                       \
        : "r"((a)[0]), "r"((a)[1]), "r"((a)[2]), "r"((a)[3]), "r"(b0), "r"(b1))

// ---------------------------------------------------------------------------
// Triangular GEMM, single-pass fp16, 5-stage cp.async pipeline (KT=64).
// 256 threads, 8 warps, warp tile 32m x 64n (4m x 2n warp grid).
// Grid: 528 lower tiles (bm-descending LPT) + 496 zero-fill tiles.
// ---------------------------------------------------------------------------
__global__ __launch_bounds__(256, 1) void trimm_kernel(float* __restrict__ C) {
    extern __shared__ char dsm[];
    const int tid = threadIdx.x;
    const int lane = tid & 31, warp = tid >> 5;

    if (blockIdx.x >= 528) {
        int u = blockIdx.x - 528, r = 0;
        #pragma unroll 1
        while (u >= 31 - r) { u -= 31 - r; r++; }
        const int m0 = r * BT, n0 = (r + 1 + u) * BT;
        const float4 z = make_float4(0.f, 0.f, 0.f, 0.f);
        #pragma unroll 1
        for (int i = tid; i < 128 * 32; i += 256)
            reinterpret_cast<float4*>(C + (size_t)(m0 + (i >> 5)) * NDIM + n0)[i & 31] = z;
        return;
    }

    // Lower-triangle tile, bm descending.
    int t = blockIdx.x, bm = 31;
    #pragma unroll 1
    while (t >= bm + 1) { t -= bm + 1; bm--; }
    const int bn = t;
    const int m0 = bm * BT, n0 = bn * BT;
    const int kbeg = n0;                          // B tril: k >= n
    const int T = (m0 + BT - kbeg) / KT;          // k64 chunks; min 2

    const uint32_t sb = smem_u32(dsm);

    // cp.async mapping: 4 cps per tile per thread. idx -> (row, 16B chunk of 8).
    const int cr0 = tid >> 3, cc = tid & 7;       // row base 0..31, chunk 0..7
    const __half* gAh = g_Ah + (size_t)(m0 + cr0) * NDIM + cc * 8;
    const __half* gBh = g_Bh + (size_t)(n0 + cr0) * NDIM + cc * 8;
    const uint32_t cdst = sb + cr0 * SROW + cc * 16;

    // Warp tile 32m x 64n.
    const int wm = (warp >> 1) * 32, wn = (warp & 1) * 64;
    uint32_t a_off[2], b_off[4];
    #pragma unroll
    for (int mi = 0; mi < 2; mi++)
        a_off[mi] = (uint32_t)((wm + mi * 16 + (lane & 15)) * SROW + (lane >> 4) * 16);
    #pragma unroll
    for (int p = 0; p < 4; p++) {
        const int quad = lane >> 3;
        b_off[p] = (uint32_t)(TILE_B + (wn + p * 16 + (quad >> 1) * 8 + (lane & 7)) * SROW +
                              (quad & 1) * 16);
    }

    float acc[2][8][4];
    #pragma unroll
    for (int mi = 0; mi < 2; mi++)
        #pragma unroll
        for (int ni = 0; ni < 8; ni++)
            #pragma unroll
            for (int r = 0; r < 4; r++) acc[mi][ni][r] = 0.f;

    // Prologue: fill up to STAGES-1 slots (T can be as small as 2).
    #pragma unroll
    for (int s = 0; s < STAGES - 1; s++) {
        if (s < T) {
            const int k0 = kbeg + s * KT;
            const uint32_t d = cdst + s * STAGE_B;
            #pragma unroll
            for (int i = 0; i < 4; i++) {
                cpa16(d + i * 32 * SROW, gAh + (size_t)i * 32 * NDIM + k0);
                cpa16(d + TILE_B + i * 32 * SROW, gBh + (size_t)i * 32 * NDIM + k0);
            }
        }
        asm volatile("cp.async.commit_group;\n");
    }

    #pragma unroll 1
    for (int it = 0; it < T; it++) {
        __syncthreads();  // all warps done with chunk it-1 (slot being reloaded)
        const int ch = it + STAGES - 1;
        if (ch < T) {
            const int k0 = kbeg + ch * KT;
            const uint32_t d = cdst + (ch % STAGES) * STAGE_B;
            #pragma unroll
            for (int i = 0; i < 4; i++) {
                cpa16(d + i * 32 * SROW, gAh + (size_t)i * 32 * NDIM + k0);
                cpa16(d + TILE_B + i * 32 * SROW, gBh + (size_t)i * 32 * NDIM + k0);
            }
        }
        asm volatile("cp.async.commit_group;\n");
        asm volatile("cp.async.wait_group %0;\n" ::"n"(STAGES - 2));
        __syncthreads();  // chunk `it` visible

        const uint32_t st = sb + (it % STAGES) * STAGE_B;
        #pragma unroll
        for (int kk = 0; kk < 4; kk++) {
            const uint32_t kb = kk * 32;  // 16 halfs = 32 bytes
            uint32_t ah[2][4], bb[4][4];
            LDSM4(ah[0][0], ah[0][1], ah[0][2], ah[0][3], st + a_off[0] + kb);
            LDSM4(ah[1][0], ah[1][1], ah[1][2], ah[1][3], st + a_off[1] + kb);
            #pragma unroll
            for (int p = 0; p < 4; p++)
                LDSM4(bb[p][0], bb[p][1], bb[p][2], bb[p][3], st + b_off[p] + kb);
            #pragma unroll
            for (int mi = 0; mi < 2; mi++)
                #pragma unroll
                for (int p = 0; p < 4; p++) {
                    MMA_F16(acc[mi][2 * p],     ah[mi], bb[p][0], bb[p][1]);
                    MMA_F16(acc[mi][2 * p + 1], ah[mi], bb[p][2], bb[p][3]);
                }
        }
    }

    // Epilogue.
    const int g = lane >> 2, tg = lane & 3;
    #pragma unroll
    for (int mi = 0; mi < 2; mi++)
        #pragma unroll
        for (int ni = 0; ni < 8; ni++) {
            const int r0 = m0 + wm + mi * 16 + g;
            const int c0 = n0 + wn + ni * 8 + tg * 2;
            *reinterpret_cast<float2*>(C + (size_t)r0 * NDIM + c0) =
                make_float2(acc[mi][ni][0], acc[mi][ni][1]);
            *reinterpret_cast<float2*>(C + (size_t)(r0 + 8) * NDIM + c0) =
                make_float2(acc[mi][ni][2], acc[mi][ni][3]);
        }
}

// ---------------------------------------------------------------------------
extern "C" void kernel_launch(void* const* d_in, const int* in_sizes, int n_in,
                              void* d_out, int out_size) {
    (void)in_sizes; (void)n_in; (void)out_size;
    const float* A = (const float*)d_in[0];
    const float* B = (const float*)d_in[1];
    float* C = (float*)d_out;

    static bool attr_done = false;
    if (!attr_done) {
        cudaFuncSetAttribute(trimm_kernel, cudaFuncAttributeMaxDynamicSharedMemorySize,
                             DSMEM_BYTES);
        attr_done = true;
    }

    convA_kernel<<<(NDIM * (size_t)NDIM) / 4 / 256, 256>>>(A);
    convB_kernel<<<dim3(NDIM / 32, NDIM / 32), dim3(32, 8)>>>(B);
    trimm_kernel<<<1024, 256, DSMEM_BYTES>>>(C);
}

// round 5
// speedup vs baseline: 3.5086x; 1.0980x over previous
#include <cuda_runtime.h>
#include <cuda_fp16.h>
#include <cstdint>
#include <cstddef>

#define NDIM   4096
#define BT     128            // C tile 128x128
#define KT     64             // k elements per pipeline stage
#define STAGES 3
#define SROW   144            // smem bytes per tile row (128B data + 16B pad)
#define TILE_B (128 * SROW)   // 18432 B
#define STAGE_B (2 * TILE_B)  // Ah + Bh = 36864 B
#define DSMEM_BYTES (STAGES * STAGE_B)  // 110592 B -> 2 CTAs/SM

// Single-pass fp16 scratch. B transposed to [n][k].
static __device__ __half g_Ah[(size_t)NDIM * NDIM];
static __device__ __half g_Bh[(size_t)NDIM * NDIM];   // [n][k]

// ---------------------------------------------------------------------------
// Fused pre-pass: blocks [0, 16384) convert A -> fp16;
//                 blocks [16384, 32768) transpose+convert B -> Bh[n][k].
// ---------------------------------------------------------------------------
__global__ void conv_kernel(const float* __restrict__ A, const float* __restrict__ B) {
    __shared__ float tile[32][33];
    const int bx = blockIdx.x;
    const int tid = threadIdx.x;

    if (bx < 16384) {
        const size_t i = (size_t)bx * 256 + tid;  // float4 index
        const float4 v = reinterpret_cast<const float4*>(A)[i];
        reinterpret_cast<ushort4*>(g_Ah)[i] =
            make_ushort4(__half_as_ushort(__float2half(v.x)),
                         __half_as_ushort(__float2half(v.y)),
                         __half_as_ushort(__float2half(v.z)),
                         __half_as_ushort(__float2half(v.w)));
        return;
    }

    const int b = bx - 16384;
    const int bk = (b & 127) * 32, bn = (b >> 7) * 32;
    const int x = tid & 31, y0 = tid >> 5;       // x:0..31, y0:0..7
    #pragma unroll
    for (int yy = y0; yy < 32; yy += 8)
        tile[yy][x] = B[(size_t)(bk + yy) * NDIM + bn + x];
    __syncthreads();
    #pragma unroll
    for (int yy = y0; yy < 32; yy += 8)
        g_Bh[(size_t)(bn + yy) * NDIM + bk + x] = __float2half(tile[x][yy]);
}

// ---------------------------------------------------------------------------
__device__ __forceinline__ uint32_t smem_u32(const void* p) {
    uint32_t a;
    asm("{ .reg .u64 t; cvta.to.shared.u64 t, %1; cvt.u32.u64 %0, t; }" : "=r"(a) : "l"(p));
    return a;
}
__device__ __forceinline__ void cpa16(uint32_t dst, const void* src) {
    asm volatile("cp.async.cg.shared.global [%0], [%1], 16;\n" ::"r"(dst), "l"(src));
}

#define LDSM4(r0, r1, r2, r3, addr)                                                    \
    asm volatile("ldmatrix.sync.aligned.m8n8.x4.shared.b16 {%0,%1,%2,%3}, [%4];"       \
                 : "=r"(r0), "=r"(r1), "=r"(r2), "=r"(r3) : "r"(addr))

#define MMA_F16(d, a, b0, b1)                                                          \
    asm volatile(                                                                      \
        "mma.sync.aligned.m16n8k16.row.col.f32.f16.f16.f32 "                           \
        "{%0,%1,%2,%3}, {%4,%5,%6,%7}, {%8,%9}, {%0,%1,%2,%3};\n"                      \
        : "+f"((d)[0]), "+f"((d)[1]), "+f"((d)[2]), "+f"((d)[3])                       \
        : "r"((a)[0]), "r"((a)[1]), "r"((a)[2]), "r"((a)[3]), "r"(b0), "r"(b1))

// ---------------------------------------------------------------------------
// Triangular GEMM, single-pass fp16, 3-stage cp.async pipeline (KT=64).
// 256 threads, 8 warps, warp tile 32m x 64n. 2 CTAs/SM.
// Grid: 528 lower tiles (bm-descending LPT) + 496 zero-fill tiles.
// ---------------------------------------------------------------------------
__global__ __launch_bounds__(256, 2) void trimm_kernel(float* __restrict__ C) {
    extern __shared__ char dsm[];
    const int tid = threadIdx.x;
    const int lane = tid & 31, warp = tid >> 5;

    if (blockIdx.x >= 528) {
        int u = blockIdx.x - 528, r = 0;
        #pragma unroll 1
        while (u >= 31 - r) { u -= 31 - r; r++; }
        const int m0 = r * BT, n0 = (r + 1 + u) * BT;
        const float4 z = make_float4(0.f, 0.f, 0.f, 0.f);
        #pragma unroll 1
        for (int i = tid; i < 128 * 32; i += 256)
            reinterpret_cast<float4*>(C + (size_t)(m0 + (i >> 5)) * NDIM + n0)[i & 31] = z;
        return;
    }

    // Lower-triangle tile, bm descending (LPT + strip reuse).
    int t = blockIdx.x, bm = 31;
    #pragma unroll 1
    while (t >= bm + 1) { t -= bm + 1; bm--; }
    const int bn = t;
    const int m0 = bm * BT, n0 = bn * BT;
    const int kbeg = n0;                          // B tril: k >= n
    const int T = (m0 + BT - kbeg) / KT;          // k64 chunks; min 2

    const uint32_t sb = smem_u32(dsm);

    // cp.async mapping: 4 cps per tile per thread.
    const int cr0 = tid >> 3, cc = tid & 7;       // row base 0..31, 16B chunk 0..7
    const __half* gAh = g_Ah + (size_t)(m0 + cr0) * NDIM + cc * 8;
    const __half* gBh = g_Bh + (size_t)(n0 + cr0) * NDIM + cc * 8;
    const uint32_t cdst = sb + cr0 * SROW + cc * 16;

    // Warp tile 32m x 64n.
    const int wm = (warp >> 1) * 32, wn = (warp & 1) * 64;
    uint32_t a_off[2], b_off[4];
    #pragma unroll
    for (int mi = 0; mi < 2; mi++)
        a_off[mi] = (uint32_t)((wm + mi * 16 + (lane & 15)) * SROW + (lane >> 4) * 16);
    #pragma unroll
    for (int p = 0; p < 4; p++) {
        const int quad = lane >> 3;
        b_off[p] = (uint32_t)(TILE_B + (wn + p * 16 + (quad >> 1) * 8 + (lane & 7)) * SROW +
                              (quad & 1) * 16);
    }

    float acc[2][8][4];
    #pragma unroll
    for (int mi = 0; mi < 2; mi++)
        #pragma unroll
        for (int ni = 0; ni < 8; ni++)
            #pragma unroll
            for (int r = 0; r < 4; r++) acc[mi][ni][r] = 0.f;

    // Prologue: fill STAGES-1 = 2 slots (T >= 2 always).
    #pragma unroll
    for (int s = 0; s < STAGES - 1; s++) {
        const int k0 = kbeg + s * KT;
        const uint32_t d = cdst + s * STAGE_B;
        #pragma unroll
        for (int i = 0; i < 4; i++) {
            cpa16(d + i * 32 * SROW, gAh + (size_t)i * 32 * NDIM + k0);
            cpa16(d + TILE_B + i * 32 * SROW, gBh + (size_t)i * 32 * NDIM + k0);
        }
        asm volatile("cp.async.commit_group;\n");
    }

    #pragma unroll 1
    for (int it = 0; it < T; it++) {
        __syncthreads();  // all warps done with chunk it-1 (slot being reloaded)
        const int ch = it + STAGES - 1;
        if (ch < T) {
            const int k0 = kbeg + ch * KT;
            const uint32_t d = cdst + (ch % STAGES) * STAGE_B;
            #pragma unroll
            for (int i = 0; i < 4; i++) {
                cpa16(d + i * 32 * SROW, gAh + (size_t)i * 32 * NDIM + k0);
                cpa16(d + TILE_B + i * 32 * SROW, gBh + (size_t)i * 32 * NDIM + k0);
            }
        }
        asm volatile("cp.async.commit_group;\n");
        asm volatile("cp.async.wait_group %0;\n" ::"n"(STAGES - 2));
        __syncthreads();  // chunk `it` visible

        const uint32_t st = sb + (it % STAGES) * STAGE_B;
        #pragma unroll
        for (int kk = 0; kk < 4; kk++) {
            const uint32_t kb = kk * 32;  // 16 halfs = 32 bytes
            uint32_t ah[2][4], bb[4][4];
            LDSM4(ah[0][0], ah[0][1], ah[0][2], ah[0][3], st + a_off[0] + kb);
            LDSM4(ah[1][0], ah[1][1], ah[1][2], ah[1][3], st + a_off[1] + kb);
            #pragma unroll
            for (int p = 0; p < 4; p++)
                LDSM4(bb[p][0], bb[p][1], bb[p][2], bb[p][3], st + b_off[p] + kb);
            #pragma unroll
            for (int mi = 0; mi < 2; mi++)
                #pragma unroll
                for (int p = 0; p < 4; p++) {
                    MMA_F16(acc[mi][2 * p],     ah[mi], bb[p][0], bb[p][1]);
                    MMA_F16(acc[mi][2 * p + 1], ah[mi], bb[p][2], bb[p][3]);
                }
        }
    }

    // Epilogue.
    const int g = lane >> 2, tg = lane & 3;
    #pragma unroll
    for (int mi = 0; mi < 2; mi++)
        #pragma unroll
        for (int ni = 0; ni < 8; ni++) {
            const int r0 = m0 + wm + mi * 16 + g;
            const int c0 = n0 + wn + ni * 8 + tg * 2;
            *reinterpret_cast<float2*>(C + (size_t)r0 * NDIM + c0) =
                make_float2(acc[mi][ni][0], acc[mi][ni][1]);
            *reinterpret_cast<float2*>(C + (size_t)(r0 + 8) * NDIM + c0) =
                make_float2(acc[mi][ni][2], acc[mi][ni][3]);
        }
}

// ---------------------------------------------------------------------------
extern "C" void kernel_launch(void* const* d_in, const int* in_sizes, int n_in,
                              void* d_out, int out_size) {
    (void)in_sizes; (void)n_in; (void)out_size;
    const float* A = (const float*)d_in[0];
    const float* B = (const float*)d_in[1];
    float* C = (float*)d_out;

    static bool attr_done = false;
    if (!attr_done) {
        cudaFuncSetAttribute(trimm_kernel, cudaFuncAttributeMaxDynamicSharedMemorySize,
                             DSMEM_BYTES);
        attr_done = true;
    }

    conv_kernel<<<32768, 256>>>(A, B);
    trimm_kernel<<<1024, 256, DSMEM_BYTES>>>(C);
}

// round 6
// speedup vs baseline: 3.9792x; 1.1341x over previous
#include <cuda_runtime.h>
#include <cuda_fp16.h>
#include <cstdint>
#include <cstddef>

#define NDIM   4096
#define BT     128            // C tile 128x128
#define KT     64             // k elements per pipeline stage
#define STAGES 3
#define SROW   144            // smem bytes per tile row (128B data + 16B pad)
#define TILE_B (128 * SROW)   // 18432 B
#define STAGE_B (2 * TILE_B)  // Ah + Bh = 36864 B
#define DSMEM_BYTES (STAGES * STAGE_B)  // 110592 B -> 2 CTAs/SM

// Single-pass fp16 scratch. B transposed to [n][k].
static __device__ __half g_Ah[(size_t)NDIM * NDIM];
static __device__ __half g_Bh[(size_t)NDIM * NDIM];   // [n][k]

// ---------------------------------------------------------------------------
// Fused pre-pass over 32x32 tiles, z=0: A -> fp16 (only tiles with ct <= rt|3,
// i.e. at/below the 128-block diagonal); z=1: B -> Bh[n][k] transpose (only
// k-tiles >= (n-tile & ~3), the part trimm reads).
// ---------------------------------------------------------------------------
__global__ void conv_kernel(const float* __restrict__ A, const float* __restrict__ B) {
    __shared__ float tile[32][33];
    const int tid = threadIdx.x;

    if (blockIdx.z == 0) {
        const int rt = blockIdx.y, ct = blockIdx.x;
        if (ct > (rt | 3)) return;                   // never read by trimm
        const int r = rt * 32 + (tid >> 3);
        const int c = ct * 32 + (tid & 7) * 4;
        const float4 v = *reinterpret_cast<const float4*>(A + (size_t)r * NDIM + c);
        *reinterpret_cast<ushort4*>(g_Ah + (size_t)r * NDIM + c) =
            make_ushort4(__half_as_ushort(__float2half(v.x)),
                         __half_as_ushort(__float2half(v.y)),
                         __half_as_ushort(__float2half(v.z)),
                         __half_as_ushort(__float2half(v.w)));
        return;
    }

    const int nt = blockIdx.y, kt = blockIdx.x;
    if (kt < (nt & ~3)) return;                      // never read by trimm
    const int bk = kt * 32, bn = nt * 32;
    const int x = tid & 31, y0 = tid >> 5;
    #pragma unroll
    for (int yy = y0; yy < 32; yy += 8)
        tile[yy][x] = B[(size_t)(bk + yy) * NDIM + bn + x];
    __syncthreads();
    #pragma unroll
    for (int yy = y0; yy < 32; yy += 8)
        g_Bh[(size_t)(bn + yy) * NDIM + bk + x] = __float2half(tile[x][yy]);
}

// ---------------------------------------------------------------------------
__device__ __forceinline__ uint32_t smem_u32(const void* p) {
    uint32_t a;
    asm("{ .reg .u64 t; cvta.to.shared.u64 t, %1; cvt.u32.u64 %0, t; }" : "=r"(a) : "l"(p));
    return a;
}
__device__ __forceinline__ void cpa16(uint32_t dst, const void* src) {
    asm volatile("cp.async.cg.shared.global [%0], [%1], 16;\n" ::"r"(dst), "l"(src));
}

#define LDSM4(r0, r1, r2, r3, addr)                                                    \
    asm volatile("ldmatrix.sync.aligned.m8n8.x4.shared.b16 {%0,%1,%2,%3}, [%4];"       \
                 : "=r"(r0), "=r"(r1), "=r"(r2), "=r"(r3) : "r"(addr))

#define MMA_F16(d, a, b0, b1)                                                          \
    asm volatile(                                                                      \
        "mma.sync.aligned.m16n8k16.row.col.f32.f16.f16.f32 "                           \
        "{%0,%1,%2,%3}, {%4,%5,%6,%7}, {%8,%9}, {%0,%1,%2,%3};\n"                      \
        : "+f"((d)[0]), "+f"((d)[1]), "+f"((d)[2]), "+f"((d)[3])                       \
        : "r"((a)[0]), "r"((a)[1]), "r"((a)[2]), "r"((a)[3]), "r"(b0), "r"(b1))

// ---------------------------------------------------------------------------
// Triangular GEMM, single-pass fp16, 3-stage cp.async pipeline (KT=64).
// ONE barrier per chunk; wait_group positioned so compute(it) only requires
// chunk it (chunks it+1, it+2 stay in flight).
// ---------------------------------------------------------------------------
__global__ __launch_bounds__(256, 2) void trimm_kernel(float* __restrict__ C) {
    extern __shared__ char dsm[];
    const int tid = threadIdx.x;
    const int lane = tid & 31, warp = tid >> 5;

    if (blockIdx.x >= 528) {
        int u = blockIdx.x - 528, r = 0;
        #pragma unroll 1
        while (u >= 31 - r) { u -= 31 - r; r++; }
        const int m0 = r * BT, n0 = (r + 1 + u) * BT;
        const float4 z = make_float4(0.f, 0.f, 0.f, 0.f);
        #pragma unroll 1
        for (int i = tid; i < 128 * 32; i += 256)
            reinterpret_cast<float4*>(C + (size_t)(m0 + (i >> 5)) * NDIM + n0)[i & 31] = z;
        return;
    }

    // Lower-triangle tile, bm descending (LPT + strip reuse).
    int t = blockIdx.x, bm = 31;
    #pragma unroll 1
    while (t >= bm + 1) { t -= bm + 1; bm--; }
    const int bn = t;
    const int m0 = bm * BT, n0 = bn * BT;
    const int kbeg = n0;                          // B tril: k >= n
    const int T = (m0 + BT - kbeg) / KT;          // k64 chunks; min 2

    const uint32_t sb = smem_u32(dsm);

    // cp.async mapping: 4 cps per tile per thread.
    const int cr0 = tid >> 3, cc = tid & 7;       // row base 0..31, 16B chunk 0..7
    const __half* gAh = g_Ah + (size_t)(m0 + cr0) * NDIM + cc * 8;
    const __half* gBh = g_Bh + (size_t)(n0 + cr0) * NDIM + cc * 8;
    const uint32_t cdst = sb + cr0 * SROW + cc * 16;

    // Warp tile 32m x 64n.
    const int wm = (warp >> 1) * 32, wn = (warp & 1) * 64;
    uint32_t a_off[2], b_off[4];
    #pragma unroll
    for (int mi = 0; mi < 2; mi++)
        a_off[mi] = (uint32_t)((wm + mi * 16 + (lane & 15)) * SROW + (lane >> 4) * 16);
    #pragma unroll
    for (int p = 0; p < 4; p++) {
        const int quad = lane >> 3;
        b_off[p] = (uint32_t)(TILE_B + (wn + p * 16 + (quad >> 1) * 8 + (lane & 7)) * SROW +
                              (quad & 1) * 16);
    }

    float acc[2][8][4];
    #pragma unroll
    for (int mi = 0; mi < 2; mi++)
        #pragma unroll
        for (int ni = 0; ni < 8; ni++)
            #pragma unroll
            for (int r = 0; r < 4; r++) acc[mi][ni][r] = 0.f;

    // Prologue: commit chunks 0,1 (T >= 2 always).
    #pragma unroll
    for (int s = 0; s < STAGES - 1; s++) {
        const int k0 = kbeg + s * KT;
        const uint32_t d = cdst + s * STAGE_B;
        #pragma unroll
        for (int i = 0; i < 4; i++) {
            cpa16(d + i * 32 * SROW, gAh + (size_t)i * 32 * NDIM + k0);
            cpa16(d + TILE_B + i * 32 * SROW, gBh + (size_t)i * 32 * NDIM + k0);
        }
        asm volatile("cp.async.commit_group;\n");
    }

    #pragma unroll 1
    for (int it = 0; it < T; it++) {
        // All but the newest 1 group done => chunk `it` resident (newest = it+1).
        asm volatile("cp.async.wait_group 1;\n");
        __syncthreads();   // chunk it visible; all warps past compute(it-1)

        // Prefetch chunk it+2 into slot (it+2)%3 == (it-1)%3 (safe per barrier).
        const int ch = it + 2;
        if (ch < T) {
            const int k0 = kbeg + ch * KT;
            const uint32_t d = cdst + (ch % STAGES) * STAGE_B;
            #pragma unroll
            for (int i = 0; i < 4; i++) {
                cpa16(d + i * 32 * SROW, gAh + (size_t)i * 32 * NDIM + k0);
                cpa16(d + TILE_B + i * 32 * SROW, gBh + (size_t)i * 32 * NDIM + k0);
            }
        }
        asm volatile("cp.async.commit_group;\n");   // always: keep group positions aligned

        const uint32_t st = sb + (it % STAGES) * STAGE_B;
        #pragma unroll
        for (int kk = 0; kk < 4; kk++) {
            const uint32_t kb = kk * 32;  // 16 halfs = 32 bytes
            uint32_t ah[2][4], bb[4][4];
            LDSM4(ah[0][0], ah[0][1], ah[0][2], ah[0][3], st + a_off[0] + kb);
            LDSM4(ah[1][0], ah[1][1], ah[1][2], ah[1][3], st + a_off[1] + kb);
            #pragma unroll
            for (int p = 0; p < 4; p++)
                LDSM4(bb[p][0], bb[p][1], bb[p][2], bb[p][3], st + b_off[p] + kb);
            #pragma unroll
            for (int mi = 0; mi < 2; mi++)
                #pragma unroll
                for (int p = 0; p < 4; p++) {
                    MMA_F16(acc[mi][2 * p],     ah[mi], bb[p][0], bb[p][1]);
                    MMA_F16(acc[mi][2 * p + 1], ah[mi], bb[p][2], bb[p][3]);
                }
        }
    }

    // Epilogue.
    const int g = lane >> 2, tg = lane & 3;
    #pragma unroll
    for (int mi = 0; mi < 2; mi++)
        #pragma unroll
        for (int ni = 0; ni < 8; ni++) {
            const int r0 = m0 + wm + mi * 16 + g;
            const int c0 = n0 + wn + ni * 8 + tg * 2;
            *reinterpret_cast<float2*>(C + (size_t)r0 * NDIM + c0) =
                make_float2(acc[mi][ni][0], acc[mi][ni][1]);
            *reinterpret_cast<float2*>(C + (size_t)(r0 + 8) * NDIM + c0) =
                make_float2(acc[mi][ni][2], acc[mi][ni][3]);
        }
}

// ---------------------------------------------------------------------------
extern "C" void kernel_launch(void* const* d_in, const int* in_sizes, int n_in,
                              void* d_out, int out_size) {
    (void)in_sizes; (void)n_in; (void)out_size;
    const float* A = (const float*)d_in[0];
    const float* B = (const float*)d_in[1];
    float* C = (float*)d_out;

    static bool attr_done = false;
    if (!attr_done) {
        cudaFuncSetAttribute(trimm_kernel, cudaFuncAttributeMaxDynamicSharedMemorySize,
                             DSMEM_BYTES);
        attr_done = true;
    }

    conv_kernel<<<dim3(128, 128, 2), 256>>>(A, B);
    trimm_kernel<<<1024, 256, DSMEM_BYTES>>>(C);
}